// round 2
// baseline (speedup 1.0000x reference)
#include <cuda_runtime.h>
#include <cstdint>

// Problem: M=8192 rows, N=8192 cols, H=4096.
//   xf    = x * weight_scale[0] * activation_scale[row]        (weight_scale[0] is a SCALAR)
//   front = xf[:, :H], back = xf[:, H:]
//   sw    = front * (back * sigmoid(back))
//   s     = sw * quant_scale[0]
//   absmax(row) -> scale = absmax/127
//   i8    = clip(rint(s/scale), -128, 127), zeroed if scale<=0
// Output buffer (float32, concatenated): [ i8 as float : M*H ][ scale : M ]

#define M_ROWS 8192
#define N_COLS 8192
#define H_COLS 4096
#define BLOCK_THREADS 256
// per thread: 4 float4 from front + 4 float4 from back -> 16 outputs

__global__ __launch_bounds__(BLOCK_THREADS, 8)
void swiglu_quant_kernel(const float* __restrict__ x,
                         const float* __restrict__ weight_scale,
                         const float* __restrict__ activation_scale,
                         const float* __restrict__ quant_scale,
                         float* __restrict__ out) {
    const int row = blockIdx.x;
    const int tid = threadIdx.x;

    const float c = weight_scale[0] * activation_scale[row];
    const float q = quant_scale[0];

    const float4* __restrict__ xrow_f =
        reinterpret_cast<const float4*>(x + (size_t)row * N_COLS);
    const float4* __restrict__ xrow_b = xrow_f + (H_COLS / 4);  // back half

    // ---- Phase 1: load both halves (front-batched for MLP), compute sw, local absmax
    float4 f[4], b[4];
#pragma unroll
    for (int k = 0; k < 4; k++) {
        const int idx = k * BLOCK_THREADS + tid;   // 0..1023 float4 slots
        f[k] = xrow_f[idx];
        b[k] = xrow_b[idx];
    }

    float s[16];
    float amax = 0.0f;
#pragma unroll
    for (int k = 0; k < 4; k++) {
        const float fl[4] = {f[k].x, f[k].y, f[k].z, f[k].w};
        const float bk[4] = {b[k].x, b[k].y, b[k].z, b[k].w};
#pragma unroll
        for (int j = 0; j < 4; j++) {
            const float lin = fl[j] * c;
            const float g   = bk[j] * c;
            const float sig = 1.0f / (1.0f + __expf(-g));
            const float v   = lin * (g * sig) * q;
            s[k * 4 + j] = v;
            amax = fmaxf(amax, fabsf(v));
        }
    }

    // ---- Phase 2: block absmax reduce (warp shuffle + smem)
    __shared__ float warp_max[BLOCK_THREADS / 32];
#pragma unroll
    for (int off = 16; off > 0; off >>= 1)
        amax = fmaxf(amax, __shfl_xor_sync(0xFFFFFFFFu, amax, off));
    const int wid = tid >> 5;
    const int lid = tid & 31;
    if (lid == 0) warp_max[wid] = amax;
    __syncthreads();
    if (wid == 0) {
        float v = (lid < BLOCK_THREADS / 32) ? warp_max[lid] : 0.0f;
#pragma unroll
        for (int off = 4; off > 0; off >>= 1)
            v = fmaxf(v, __shfl_xor_sync(0xFFFFFFFFu, v, off));
        if (lid == 0) warp_max[0] = v;
    }
    __syncthreads();
    const float absmax = warp_max[0];
    const float scale  = absmax * (1.0f / 127.0f);
    const float inv    = (scale > 0.0f) ? (1.0f / scale) : 0.0f;  // inv=0 -> i8=0 (matches ref)

    // ---- Phase 3: quantize from registers, vectorized store
    float4* __restrict__ orow = reinterpret_cast<float4*>(out + (size_t)row * H_COLS);
#pragma unroll
    for (int k = 0; k < 4; k++) {
        float4 o;
        float vv[4];
#pragma unroll
        for (int j = 0; j < 4; j++) {
            float r = rintf(s[k * 4 + j] * inv);         // round-half-to-even == jnp.round
            r = fminf(fmaxf(r, -128.0f), 127.0f);
            vv[j] = r;
        }
        o.x = vv[0]; o.y = vv[1]; o.z = vv[2]; o.w = vv[3];
        orow[k * BLOCK_THREADS + tid] = o;
    }

    if (tid == 0) {
        out[(size_t)M_ROWS * H_COLS + row] = scale;
    }
}

extern "C" void kernel_launch(void* const* d_in, const int* in_sizes, int n_in,
                              void* d_out, int out_size) {
    const float* x  = (const float*)d_in[0];
    const float* ws = (const float*)d_in[1];
    const float* as = (const float*)d_in[2];
    const float* qs = (const float*)d_in[3];
    float* out = (float*)d_out;
    (void)in_sizes; (void)n_in; (void)out_size;

    swiglu_quant_kernel<<<M_ROWS, BLOCK_THREADS>>>(x, ws, as, qs, out);
}

// round 3
// speedup vs baseline: 1.0034x; 1.0034x over previous
#include <cuda_runtime.h>
#include <cstdint>

// M=8192 rows, N=8192 cols, H=4096.
//   xf    = x * weight_scale[0] * activation_scale[row]
//   sw    = front * (back * sigmoid(back)),  s = sw * quant_scale[0]
//   scale = rowmax(|s|)/127;  i8 = clip(rint(s/scale), -128, 127)  (0 if scale<=0)
// Output (float32): [ i8 as float : M*H ][ scale : M ]
//
// Persistent grid-stride pipeline: 592 CTAs (148 SMs x 4), each CTA walks rows
// with stride 592 and prefetches the NEXT row's 8x LDG.128 before the current
// row's reduce barriers + stores, so DRAM never drains.

#define M_ROWS 8192
#define N_COLS 8192
#define H_COLS 4096
#define BLOCK_THREADS 256
#define GRID_CTAS (148 * 4)

__device__ __forceinline__ void load_row(const float* __restrict__ x, int row,
                                         int tid, float4 (&f)[4], float4 (&b)[4]) {
    const float4* __restrict__ xf =
        reinterpret_cast<const float4*>(x + (size_t)row * N_COLS);
    const float4* __restrict__ xb = xf + (H_COLS / 4);
#pragma unroll
    for (int k = 0; k < 4; k++) {
        const int idx = k * BLOCK_THREADS + tid;
        f[k] = __ldcs(&xf[idx]);   // streaming: no reuse, evict-first
        b[k] = __ldcs(&xb[idx]);
    }
}

__global__ __launch_bounds__(BLOCK_THREADS, 4)
void swiglu_quant_kernel(const float* __restrict__ x,
                         const float* __restrict__ weight_scale,
                         const float* __restrict__ activation_scale,
                         const float* __restrict__ quant_scale,
                         float* __restrict__ out) {
    const int tid = threadIdx.x;
    const int wid = tid >> 5;
    const int lid = tid & 31;

    __shared__ float warp_max[BLOCK_THREADS / 32];
    __shared__ float bcast[2];          // [0]=scale, [1]=inv

    const float wsc = weight_scale[0];
    const float q   = quant_scale[0];

    int row = blockIdx.x;

    // Prologue: prefetch first row
    float4 f[4], b[4];
    load_row(x, row, tid, f, b);

    while (row < M_ROWS) {
        const int next = row + GRID_CTAS;
        const float c = wsc * activation_scale[row];

        // ---- compute SwiGLU + local absmax from registers (f/b die here)
        float s[16];
        float amax = 0.0f;
#pragma unroll
        for (int k = 0; k < 4; k++) {
            const float fl[4] = {f[k].x, f[k].y, f[k].z, f[k].w};
            const float bk[4] = {b[k].x, b[k].y, b[k].z, b[k].w};
#pragma unroll
            for (int j = 0; j < 4; j++) {
                const float lin = fl[j] * c;
                const float g   = bk[j] * c;
                const float sig = 1.0f / (1.0f + __expf(-g));
                const float v   = lin * (g * sig) * q;
                s[k * 4 + j] = v;
                amax = fmaxf(amax, fabsf(v));
            }
        }

        // ---- prefetch NEXT row into the now-dead f/b regs, BEFORE the barriers
        if (next < M_ROWS) load_row(x, next, tid, f, b);

        // ---- block absmax reduce; one thread computes scale + inv, broadcasts
#pragma unroll
        for (int off = 16; off > 0; off >>= 1)
            amax = fmaxf(amax, __shfl_xor_sync(0xFFFFFFFFu, amax, off));
        if (lid == 0) warp_max[wid] = amax;
        __syncthreads();
        if (wid == 0) {
            float v = (lid < BLOCK_THREADS / 32) ? warp_max[lid] : 0.0f;
#pragma unroll
            for (int off = 4; off > 0; off >>= 1)
                v = fmaxf(v, __shfl_xor_sync(0xFFFFFFFFu, v, off));
            if (lid == 0) {
                const float scale = v * (1.0f / 127.0f);
                bcast[0] = scale;
                bcast[1] = (scale > 0.0f) ? (1.0f / scale) : 0.0f;
            }
        }
        __syncthreads();
        const float scale = bcast[0];
        const float inv   = bcast[1];

        // ---- quantize + streaming stores
        float4* __restrict__ orow = reinterpret_cast<float4*>(out + (size_t)row * H_COLS);
#pragma unroll
        for (int k = 0; k < 4; k++) {
            float4 o;
            o.x = fminf(fmaxf(rintf(s[k * 4 + 0] * inv), -128.0f), 127.0f);
            o.y = fminf(fmaxf(rintf(s[k * 4 + 1] * inv), -128.0f), 127.0f);
            o.z = fminf(fmaxf(rintf(s[k * 4 + 2] * inv), -128.0f), 127.0f);
            o.w = fminf(fmaxf(rintf(s[k * 4 + 3] * inv), -128.0f), 127.0f);
            __stcs(&orow[k * BLOCK_THREADS + tid], o);
        }
        if (tid == 0) {
            out[(size_t)M_ROWS * H_COLS + row] = scale;
        }

        row = next;
    }
}

extern "C" void kernel_launch(void* const* d_in, const int* in_sizes, int n_in,
                              void* d_out, int out_size) {
    const float* x  = (const float*)d_in[0];
    const float* ws = (const float*)d_in[1];
    const float* as = (const float*)d_in[2];
    const float* qs = (const float*)d_in[3];
    float* out = (float*)d_out;
    (void)in_sizes; (void)n_in; (void)out_size;

    swiglu_quant_kernel<<<GRID_CTAS, BLOCK_THREADS>>>(x, ws, as, qs, out);
}

// round 4
// speedup vs baseline: 1.0073x; 1.0039x over previous
#include <cuda_runtime.h>
#include <cstdint>

// M=8192 rows, N=8192 cols, H=4096.
//   xf    = x * weight_scale[0] * activation_scale[row]
//   sw    = front * (back * sigmoid(back)),  s = sw * quant_scale[0]
//   scale = rowmax(|s|)/127;  i8 = clip(rint(s/scale), -128, 127)  (0 if scale<=0)
// Output (float32): [ i8 as float : M*H ][ scale : M ]
//
// Persistent full-occupancy kernel: 1184 CTAs (148 SMs x 8), grid-stride over
// rows. One barrier per row: warp absmax via redux.sync, each thread folds the
// 8 warp maxima itself (smem parity-double-buffered to avoid a 2nd barrier).
// Kernel is at the chip LTS cap (~6.3 TB/s); this round shaves barrier/imbalance
// /ALU overhead so the cap is held for the whole duration.

#define M_ROWS 8192
#define N_COLS 8192
#define H_COLS 4096
#define BLOCK_THREADS 256
#define N_WARPS (BLOCK_THREADS / 32)
#define GRID_CTAS (148 * 8)

__global__ __launch_bounds__(BLOCK_THREADS, 8)
void swiglu_quant_kernel(const float* __restrict__ x,
                         const float* __restrict__ activation_scale,
                         const float* __restrict__ weight_scale,
                         const float* __restrict__ quant_scale,
                         float* __restrict__ out) {
    const int tid = threadIdx.x;
    const int wid = tid >> 5;

    __shared__ float warp_max[2][N_WARPS];   // parity double-buffer

    const float wsc = weight_scale[0];
    const float q   = quant_scale[0];

    int row = blockIdx.x;
    int parity = 0;

    // Row-base pointers, advanced by pointer increments (cuts 64-bit remul ALU)
    const float4* __restrict__ pf =
        reinterpret_cast<const float4*>(x + (size_t)row * N_COLS) + tid;
    const float4* __restrict__ pb = pf + (H_COLS / 4);
    float4* __restrict__ po =
        reinterpret_cast<float4*>(out + (size_t)row * H_COLS) + tid;
    float* __restrict__ pscale = out + (size_t)M_ROWS * H_COLS;

    const ptrdiff_t stride_in  = (ptrdiff_t)GRID_CTAS * (N_COLS / 4);
    const ptrdiff_t stride_out = (ptrdiff_t)GRID_CTAS * (H_COLS / 4);

    for (; row < M_ROWS; row += GRID_CTAS,
                         pf += stride_in, pb += stride_in, po += stride_out) {
        const float c = wsc * activation_scale[row];

        // ---- load + SwiGLU + thread-local absmax
        float s[16];
        float amax = 0.0f;
#pragma unroll
        for (int k = 0; k < 4; k++) {
            const float4 f = __ldcs(pf + k * BLOCK_THREADS);
            const float4 b = __ldcs(pb + k * BLOCK_THREADS);
            const float fl[4] = {f.x, f.y, f.z, f.w};
            const float bk[4] = {b.x, b.y, b.z, b.w};
#pragma unroll
            for (int j = 0; j < 4; j++) {
                const float lin = fl[j] * c;
                const float g   = bk[j] * c;
                const float sig = 1.0f / (1.0f + __expf(-g));
                const float v   = lin * (g * sig) * q;
                s[k * 4 + j] = v;
                amax = fmaxf(amax, fabsf(v));
            }
        }

        // ---- warp absmax: nonnegative floats are bit-monotone -> u32 redux
        unsigned wmax = __reduce_max_sync(0xFFFFFFFFu, __float_as_uint(amax));
        if ((tid & 31) == 0) warp_max[parity][wid] = __uint_as_float(wmax);
        __syncthreads();   // the ONLY barrier per row

        // every thread folds the 8 warp maxima itself (LDS broadcast, no 2nd bar)
        float m = warp_max[parity][0];
#pragma unroll
        for (int w = 1; w < N_WARPS; w++) m = fmaxf(m, warp_max[parity][w]);
        const float scale = m * (1.0f / 127.0f);
        const float inv   = (scale > 0.0f) ? (1.0f / scale) : 0.0f;

        // ---- quantize + streaming stores
#pragma unroll
        for (int k = 0; k < 4; k++) {
            float4 o;
            o.x = fminf(fmaxf(rintf(s[k * 4 + 0] * inv), -128.0f), 127.0f);
            o.y = fminf(fmaxf(rintf(s[k * 4 + 1] * inv), -128.0f), 127.0f);
            o.z = fminf(fmaxf(rintf(s[k * 4 + 2] * inv), -128.0f), 127.0f);
            o.w = fminf(fmaxf(rintf(s[k * 4 + 3] * inv), -128.0f), 127.0f);
            __stcs(po + k * BLOCK_THREADS, o);
        }
        if (tid == 0) pscale[row] = scale;

        parity ^= 1;
    }
}

extern "C" void kernel_launch(void* const* d_in, const int* in_sizes, int n_in,
                              void* d_out, int out_size) {
    const float* x  = (const float*)d_in[0];
    const float* ws = (const float*)d_in[1];
    const float* as = (const float*)d_in[2];
    const float* qs = (const float*)d_in[3];
    float* out = (float*)d_out;
    (void)in_sizes; (void)n_in; (void)out_size;

    swiglu_quant_kernel<<<GRID_CTAS, BLOCK_THREADS>>>(x, as, ws, qs, out);
}

// round 5
// speedup vs baseline: 1.0078x; 1.0005x over previous
#include <cuda_runtime.h>
#include <cstdint>

// M=8192 rows, N=8192 cols, H=4096.
//   xf    = x * weight_scale[0] * activation_scale[row]
//   sw    = front * (back * sigmoid(back)),  s = sw * quant_scale[0]
//   scale = rowmax(|s|)/127;  i8 = clip(rint(s/scale), -128, 127)  (0 if scale<=0)
// Output (float32): [ i8 as float : M*H ][ scale : M ]
//
// One CTA per row (8192 CTAs x 256 thr, occ 8/SM) — empirically the best
// memory shape (R1: DRAM 76.6%). Single barrier per CTA: warp absmax via
// redux.sync.max.u32, each thread folds the 8 warp maxima from smem itself.
// Kernel is at the chip LTS cap (~6300 B/cyc path-independent); everything
// else is minimized around that.

#define M_ROWS 8192
#define N_COLS 8192
#define H_COLS 4096
#define BLOCK_THREADS 256
#define N_WARPS (BLOCK_THREADS / 32)

__global__ __launch_bounds__(BLOCK_THREADS, 8)
void swiglu_quant_kernel(const float* __restrict__ x,
                         const float* __restrict__ weight_scale,
                         const float* __restrict__ activation_scale,
                         const float* __restrict__ quant_scale,
                         float* __restrict__ out) {
    const int row = blockIdx.x;
    const int tid = threadIdx.x;

    __shared__ float warp_max[N_WARPS];

    const float c = weight_scale[0] * activation_scale[row];
    const float q = quant_scale[0];

    const float4* __restrict__ pf =
        reinterpret_cast<const float4*>(x + (size_t)row * N_COLS) + tid;
    const float4* __restrict__ pb = pf + (H_COLS / 4);

    // ---- load (front-batched LDG.128s), SwiGLU, thread-local absmax
    float4 f[4], b[4];
#pragma unroll
    for (int k = 0; k < 4; k++) {
        f[k] = __ldcs(pf + k * BLOCK_THREADS);
        b[k] = __ldcs(pb + k * BLOCK_THREADS);
    }

    float s[16];
    float amax = 0.0f;
#pragma unroll
    for (int k = 0; k < 4; k++) {
        const float fl[4] = {f[k].x, f[k].y, f[k].z, f[k].w};
        const float bk[4] = {b[k].x, b[k].y, b[k].z, b[k].w};
#pragma unroll
        for (int j = 0; j < 4; j++) {
            const float lin = fl[j] * c;
            const float g   = bk[j] * c;
            const float sig = 1.0f / (1.0f + __expf(-g));
            const float v   = lin * (g * sig) * q;
            s[k * 4 + j] = v;
            amax = fmaxf(amax, fabsf(v));
        }
    }

    // ---- absmax reduce: redux per warp, ONE barrier, every thread folds 8
    unsigned wmax = __reduce_max_sync(0xFFFFFFFFu, __float_as_uint(amax));
    if ((tid & 31) == 0) warp_max[tid >> 5] = __uint_as_float(wmax);
    __syncthreads();

    float m = warp_max[0];
#pragma unroll
    for (int w = 1; w < N_WARPS; w++) m = fmaxf(m, warp_max[w]);
    const float scale = m * (1.0f / 127.0f);
    const float inv   = (scale > 0.0f) ? (1.0f / scale) : 0.0f;

    // ---- quantize + streaming stores
    float4* __restrict__ po =
        reinterpret_cast<float4*>(out + (size_t)row * H_COLS) + tid;
#pragma unroll
    for (int k = 0; k < 4; k++) {
        float4 o;
        o.x = fminf(fmaxf(rintf(s[k * 4 + 0] * inv), -128.0f), 127.0f);
        o.y = fminf(fmaxf(rintf(s[k * 4 + 1] * inv), -128.0f), 127.0f);
        o.z = fminf(fmaxf(rintf(s[k * 4 + 2] * inv), -128.0f), 127.0f);
        o.w = fminf(fmaxf(rintf(s[k * 4 + 3] * inv), -128.0f), 127.0f);
        __stcs(po + k * BLOCK_THREADS, o);
    }
    if (tid == 0) {
        out[(size_t)M_ROWS * H_COLS + row] = scale;
    }
}

extern "C" void kernel_launch(void* const* d_in, const int* in_sizes, int n_in,
                              void* d_out, int out_size) {
    const float* x  = (const float*)d_in[0];
    const float* ws = (const float*)d_in[1];
    const float* as = (const float*)d_in[2];
    const float* qs = (const float*)d_in[3];
    float* out = (float*)d_out;
    (void)in_sizes; (void)n_in; (void)out_size;

    swiglu_quant_kernel<<<M_ROWS, BLOCK_THREADS>>>(x, ws, as, qs, out);
}